// round 1
// baseline (speedup 1.0000x reference)
#include <cuda_runtime.h>
#include <math.h>

// ---------------------------------------------------------------------------
// DeformableConv2d: B=8, C=112, H=W=64, O=112, K=3, G=14, stride=1, pad=1
// pg channels: 378 = 252 offsets (interleaved dy/dx per (g,k)) + 126 mask
// ---------------------------------------------------------------------------

#define BB 8
#define CC 112
#define HH 64
#define WW 64
#define OO 112
#define GG 14
#define K2 9
#define PGC 378            // 3*G*K2
#define HW 4096            // 64*64
#define CK 1008            // C*K2

// scratch (allocation-free rule: static __device__ arrays)
__device__ float g_pg[BB * PGC * HW];          // 47.25 MiB
__device__ float g_smp[BB * CC * K2 * HW];     // 126 MiB

// ---------------------------------------------------------------------------
// Kernel 1: pg = conv3x3(x, pg_weight, pad=1) + pg_bias
// Block: 256 threads -> 64 output channels x 64 pixels (one row), one (b,oh).
// Loop input channels in chunks of 8. Each thread: 4 oc x 4 px register tile.
// ---------------------------------------------------------------------------
__global__ __launch_bounds__(256) void k1_pgconv(const float* __restrict__ x,
                                                 const float* __restrict__ pw,
                                                 const float* __restrict__ pb)
{
    const int ocTile = blockIdx.x;     // 0..5  (6*64 = 384 >= 378)
    const int oh     = blockIdx.y;     // 0..63
    const int b      = blockIdx.z;     // 0..7
    const int t      = threadIdx.x;
    const int pxg    = t & 15;         // 16 pixel groups * 4 px
    const int ocg    = t >> 4;         // 16 oc groups * 4 oc
    const int px0    = pxg * 4;
    const int ocl0   = ocg * 4;
    const int oc0    = ocTile * 64;

    __shared__ float xs[3][8][66];
    __shared__ __align__(16) float ws[72 * 68];

    float acc[4][4];
#pragma unroll
    for (int j = 0; j < 4; ++j)
#pragma unroll
        for (int i = 0; i < 4; ++i) acc[j][i] = 0.f;

    for (int c0 = 0; c0 < CC; c0 += 8) {
        __syncthreads();
        // ---- load input tile: 3 rows x 8 chans x 66 cols (halo, zero-padded)
        for (int idx = t; idx < 3 * 8 * 66; idx += 256) {
            int ky  = idx / (8 * 66);
            int rem = idx - ky * (8 * 66);
            int cl  = rem / 66;
            int col = rem - cl * 66;
            int ih  = oh - 1 + ky;
            int iw  = col - 1;
            float v = 0.f;
            if ((unsigned)ih < 64u && (unsigned)iw < 64u)
                v = x[(((size_t)b * CC + c0 + cl) * HH + ih) * WW + iw];
            xs[ky][cl][col] = v;
        }
        // ---- load weight tile: 64 oc x (8 c * 9 taps), stored [ck][oc] pad 68
        for (int idx = t; idx < 64 * 72; idx += 256) {
            int ocl = idx / 72;
            int ck  = idx - ocl * 72;
            int oc  = oc0 + ocl;
            float v = (oc < PGC) ? pw[(size_t)oc * CK + c0 * 9 + ck] : 0.f;
            ws[ck * 68 + ocl] = v;
        }
        __syncthreads();

        for (int cl = 0; cl < 8; ++cl) {
#pragma unroll
            for (int ky = 0; ky < 3; ++ky) {
                float xv[6];
#pragma unroll
                for (int i = 0; i < 6; ++i) xv[i] = xs[ky][cl][px0 + i];
#pragma unroll
                for (int kx = 0; kx < 3; ++kx) {
                    const float4 wv =
                        *(const float4*)(&ws[(cl * 9 + ky * 3 + kx) * 68 + ocl0]);
#pragma unroll
                    for (int i = 0; i < 4; ++i) {
                        acc[0][i] = fmaf(wv.x, xv[i + kx], acc[0][i]);
                        acc[1][i] = fmaf(wv.y, xv[i + kx], acc[1][i]);
                        acc[2][i] = fmaf(wv.z, xv[i + kx], acc[2][i]);
                        acc[3][i] = fmaf(wv.w, xv[i + kx], acc[3][i]);
                    }
                }
            }
        }
    }

#pragma unroll
    for (int j = 0; j < 4; ++j) {
        int oc = oc0 + ocl0 + j;
        if (oc < PGC) {
            float bv = pb[oc];
            float* dst = &g_pg[(((size_t)b * PGC + oc) * HH + oh) * WW + px0];
#pragma unroll
            for (int i = 0; i < 4; ++i) dst[i] = acc[j][i] + bv;
        }
    }
}

// ---------------------------------------------------------------------------
// Kernel 2: bilinear sampling * sigmoid(mask)
// One thread per (b, g, k, pixel): computes bilinear weights once, samples the
// 8 channels of group g.  dy = pg[g*18+2k], dx = pg[g*18+2k+1] (interleaved!),
// mask = sigmoid(pg[252 + g*9 + k]).
// Output layout: g_smp[b][c][k][p]  (ck = c*9+k contiguous for the GEMM)
// ---------------------------------------------------------------------------
__global__ __launch_bounds__(256) void k2_sample(const float* __restrict__ x)
{
    int gid = blockIdx.x * 256 + threadIdx.x;
    const int TOT = BB * GG * K2 * HW;   // 4,128,768
    if (gid >= TOT) return;

    int p    = gid & (HW - 1);
    int rest = gid >> 12;
    int gk   = rest % (GG * K2);
    int b    = rest / (GG * K2);
    int g    = gk / 9;
    int k    = gk - g * 9;
    int oh   = p >> 6, ow = p & 63;

    const float* pgb = g_pg + (size_t)b * PGC * HW;
    float dy = pgb[(g * 18 + 2 * k) * HW + p];
    float dx = pgb[(g * 18 + 2 * k + 1) * HW + p];
    float m  = pgb[(252 + gk) * HW + p];
    float mask = 1.f / (1.f + expf(-m));

    float yy = (float)(oh - 1 + k / 3) + dy;
    float xx = (float)(ow - 1 + k % 3) + dx;
    float y0f = floorf(yy), x0f = floorf(xx);
    float wy1 = yy - y0f, wx1 = xx - x0f;
    float wy0 = 1.f - wy1, wx0 = 1.f - wx1;
    int y0 = (int)y0f, x0i = (int)x0f;
    int y1 = y0 + 1, x1 = x0i + 1;
    bool vy0 = (unsigned)y0 < 64u, vy1 = (unsigned)y1 < 64u;
    bool vx0 = (unsigned)x0i < 64u, vx1 = (unsigned)x1 < 64u;

    float w00 = (vy0 && vx0) ? wy0 * wx0 * mask : 0.f;
    float w01 = (vy0 && vx1) ? wy0 * wx1 * mask : 0.f;
    float w10 = (vy1 && vx0) ? wy1 * wx0 * mask : 0.f;
    float w11 = (vy1 && vx1) ? wy1 * wx1 * mask : 0.f;

    int yc0 = min(max(y0, 0), 63), yc1 = min(max(y1, 0), 63);
    int xc0 = min(max(x0i, 0), 63), xc1 = min(max(x1, 0), 63);
    int i00 = yc0 * 64 + xc0, i01 = yc0 * 64 + xc1;
    int i10 = yc1 * 64 + xc0, i11 = yc1 * 64 + xc1;

    const float* xb = x + ((size_t)b * CC + g * 8) * HW;
    float* out = g_smp + ((((size_t)b * CC + g * 8) * K2) + k) * HW + p;
#pragma unroll
    for (int c = 0; c < 8; ++c) {
        const float* xc = xb + (size_t)c * HW;
        float v = w00 * xc[i00] + w01 * xc[i01] + w10 * xc[i10] + w11 * xc[i11];
        out[(size_t)c * K2 * HW] = v;
    }
}

// ---------------------------------------------------------------------------
// Kernel 3: out[b,o,p] = bias[o] + sum_ck smp[b,ck,p] * W[o,ck]
// Block: 256 threads -> all 112 O x 32 px. Each thread: 7 oc x 2 px.
// ---------------------------------------------------------------------------
__global__ __launch_bounds__(256) void k3_gemm(const float* __restrict__ w2,
                                               const float* __restrict__ bias,
                                               float* __restrict__ out)
{
    const int pt = blockIdx.x;       // 0..127
    const int b  = blockIdx.y;       // 0..7
    const int t  = threadIdx.x;
    const int pxg = t & 15;          // 16 groups * 2 px
    const int ocg = t >> 4;          // 16 groups * 7 oc
    const int p0  = pt * 32;

    __shared__ float ss[16 * 32];
    __shared__ float ws2[16 * 113];

    float acc[7][2];
#pragma unroll
    for (int j = 0; j < 7; ++j) { acc[j][0] = 0.f; acc[j][1] = 0.f; }

    const float* sb = g_smp + (size_t)b * CK * HW + p0;

    for (int ck0 = 0; ck0 < CK; ck0 += 16) {
        __syncthreads();
        {
            int idx = t;
#pragma unroll
            for (int r = 0; r < 2; ++r, idx += 256) {
                int ckl = idx >> 5, pxl = idx & 31;
                ss[ckl * 32 + pxl] = sb[(size_t)(ck0 + ckl) * HW + pxl];
            }
        }
        for (int idx = t; idx < 16 * 112; idx += 256) {
            int o = idx >> 4, ckl = idx & 15;
            ws2[ckl * 113 + o] = w2[(size_t)o * CK + ck0 + ckl];
        }
        __syncthreads();

#pragma unroll
        for (int ckl = 0; ckl < 16; ++ckl) {
            float s0 = ss[ckl * 32 + pxg * 2];
            float s1 = ss[ckl * 32 + pxg * 2 + 1];
            const float* wr = &ws2[ckl * 113 + ocg * 7];
#pragma unroll
            for (int j = 0; j < 7; ++j) {
                float wv = wr[j];
                acc[j][0] = fmaf(wv, s0, acc[j][0]);
                acc[j][1] = fmaf(wv, s1, acc[j][1]);
            }
        }
    }

#pragma unroll
    for (int j = 0; j < 7; ++j) {
        int o = ocg * 7 + j;
        float bv = bias[o];
        float* dst = &out[(((size_t)b * OO + o) * HW) + p0 + pxg * 2];
        dst[0] = acc[j][0] + bv;
        dst[1] = acc[j][1] + bv;
    }
}

// ---------------------------------------------------------------------------
extern "C" void kernel_launch(void* const* d_in, const int* in_sizes, int n_in,
                              void* d_out, int out_size)
{
    const float* x  = (const float*)d_in[0];   // (8,112,64,64)
    const float* pw = (const float*)d_in[1];   // (378,112,3,3)
    const float* pb = (const float*)d_in[2];   // (378,)
    const float* w  = (const float*)d_in[3];   // (112,112,3,3)
    const float* bs = (const float*)d_in[4];   // (112,)
    float* out = (float*)d_out;                // (8,112,64,64)

    dim3 g1(6, 64, 8);
    k1_pgconv<<<g1, 256>>>(x, pw, pb);

    const int tot2 = BB * GG * K2 * HW;
    k2_sample<<<(tot2 + 255) / 256, 256>>>(x);

    dim3 g3(128, 8);
    k3_gemm<<<g3, 256>>>(w, bs, out);
}

// round 2
// speedup vs baseline: 1.2142x; 1.2142x over previous
#include <cuda_runtime.h>
#include <math.h>

// ---------------------------------------------------------------------------
// DeformableConv2d: B=8, C=112, H=W=64, O=112, K=3, G=14, stride=1, pad=1
// pg channels: 378 = 252 offsets (interleaved dy/dx per (g,k)) + 126 mask
// ---------------------------------------------------------------------------

#define BB 8
#define CC 112
#define HH 64
#define WW 64
#define OO 112
#define GG 14
#define K2 9
#define PGC 378            // 3*G*K2
#define HW 4096            // 64*64
#define CK 1008            // C*K2

// scratch (allocation-free rule: static __device__ arrays)
__device__ float g_pg[BB * PGC * HW];          // 47.25 MiB
__device__ float g_smp[BB * CC * K2 * HW];     // 126 MiB

// ---------------------------------------------------------------------------
// Kernel 1: pg = conv3x3(x, pg_weight, pad=1) + pg_bias
// Block: 256 threads -> 64 oc x 128 px (2 output rows). c-chunks of 8.
// Thread tile: 4 oc x 8 contiguous px. All fill indexing is shift/and only.
// ---------------------------------------------------------------------------
__global__ __launch_bounds__(256) void k1_pgconv(const float* __restrict__ x,
                                                 const float* __restrict__ pw,
                                                 const float* __restrict__ pb)
{
    const int ocTile = blockIdx.x;     // 0..5  (6*64 = 384 >= 378)
    const int rp     = blockIdx.y;     // 0..31 row pair
    const int b      = blockIdx.z;     // 0..7
    const int t      = threadIdx.x;
    const int oh0    = rp * 2;

    const int pg   = t & 15;           // 16 pixel groups
    const int og   = t >> 4;           // 16 oc groups
    const int r    = pg >> 3;          // 0/1 : which output row
    const int col0 = (pg & 7) * 8;     // 8 contiguous columns
    const int ocl0 = og * 4;
    const int oc0  = ocTile * 64;

    // xs rows: input rows oh0-1 .. oh0+2
    __shared__ float xs[4][8][66];
    __shared__ __align__(16) float ws[72 * 68];

    // halo columns (iw=-1 and iw=64) are always out of bounds -> zero once
    if (t < 64) {
        int rr = t >> 4, cl = (t >> 1) & 7, side = t & 1;
        xs[rr][cl][side * 65] = 0.f;
    }

    float acc[4][8];
#pragma unroll
    for (int j = 0; j < 4; ++j)
#pragma unroll
        for (int i = 0; i < 8; ++i) acc[j][i] = 0.f;

    for (int c0 = 0; c0 < CC; c0 += 8) {
        __syncthreads();
        // ---- input tile: 4 rows x 8 ch x 64 inner cols (2048 = 8*256)
        {
            int idx = t;
#pragma unroll
            for (int i = 0; i < 8; ++i, idx += 256) {
                int col = idx & 63;
                int cl  = (idx >> 6) & 7;
                int rr  = idx >> 9;
                int ih  = oh0 - 1 + rr;
                float v = 0.f;
                if ((unsigned)ih < 64u)
                    v = x[(((size_t)b * CC + c0 + cl) * HH + ih) * WW + col];
                xs[rr][cl][col + 1] = v;
            }
        }
        // ---- weight tile: 72 ck x 64 oc (4608 = 18*256), [ck][oc] pad 68
        {
            int idx = t;
#pragma unroll
            for (int i = 0; i < 18; ++i, idx += 256) {
                int ocl = idx & 63;
                int ck  = idx >> 6;
                int oc  = oc0 + ocl;
                float v = (oc < PGC) ? pw[(size_t)oc * CK + c0 * 9 + ck] : 0.f;
                ws[ck * 68 + ocl] = v;
            }
        }
        __syncthreads();

#pragma unroll
        for (int cl = 0; cl < 8; ++cl) {
#pragma unroll
            for (int ky = 0; ky < 3; ++ky) {
                float xv[10];
                const float* xrow = &xs[r + ky][cl][col0];
#pragma unroll
                for (int i = 0; i < 10; ++i) xv[i] = xrow[i];
#pragma unroll
                for (int kx = 0; kx < 3; ++kx) {
                    const float4 wv =
                        *(const float4*)(&ws[(cl * 9 + ky * 3 + kx) * 68 + ocl0]);
#pragma unroll
                    for (int i = 0; i < 8; ++i) {
                        acc[0][i] = fmaf(wv.x, xv[i + kx], acc[0][i]);
                        acc[1][i] = fmaf(wv.y, xv[i + kx], acc[1][i]);
                        acc[2][i] = fmaf(wv.z, xv[i + kx], acc[2][i]);
                        acc[3][i] = fmaf(wv.w, xv[i + kx], acc[3][i]);
                    }
                }
            }
        }
    }

#pragma unroll
    for (int j = 0; j < 4; ++j) {
        int oc = oc0 + ocl0 + j;
        if (oc < PGC) {
            float bv = pb[oc];
            float* dst = &g_pg[(((size_t)b * PGC + oc) * HH + oh0 + r) * WW + col0];
            float4 v0 = make_float4(acc[j][0] + bv, acc[j][1] + bv,
                                    acc[j][2] + bv, acc[j][3] + bv);
            float4 v1 = make_float4(acc[j][4] + bv, acc[j][5] + bv,
                                    acc[j][6] + bv, acc[j][7] + bv);
            *(float4*)(dst)     = v0;
            *(float4*)(dst + 4) = v1;
        }
    }
}

// ---------------------------------------------------------------------------
// Kernel 2: bilinear sampling * sigmoid(mask)
// One thread per (b, g, k, pixel). dy = pg[g*18+2k], dx = pg[g*18+2k+1]
// (interleaved!), mask = sigmoid(pg[252 + g*9 + k]).
// Output layout: g_smp[b][c][k][p]
// ---------------------------------------------------------------------------
__global__ __launch_bounds__(256) void k2_sample(const float* __restrict__ x)
{
    int gid = blockIdx.x * 256 + threadIdx.x;
    const int TOT = BB * GG * K2 * HW;   // 4,128,768
    if (gid >= TOT) return;

    int p    = gid & (HW - 1);
    int rest = gid >> 12;
    int gk   = rest % (GG * K2);
    int b    = rest / (GG * K2);
    int g    = gk / 9;
    int k    = gk - g * 9;
    int oh   = p >> 6, ow = p & 63;

    const float* pgb = g_pg + (size_t)b * PGC * HW;
    float dy = pgb[(g * 18 + 2 * k) * HW + p];
    float dx = pgb[(g * 18 + 2 * k + 1) * HW + p];
    float m  = pgb[(252 + gk) * HW + p];
    float mask = 1.f / (1.f + expf(-m));

    float yy = (float)(oh - 1 + k / 3) + dy;
    float xx = (float)(ow - 1 + k % 3) + dx;
    float y0f = floorf(yy), x0f = floorf(xx);
    float wy1 = yy - y0f, wx1 = xx - x0f;
    float wy0 = 1.f - wy1, wx0 = 1.f - wx1;
    int y0 = (int)y0f, x0i = (int)x0f;
    int y1 = y0 + 1, x1 = x0i + 1;
    bool vy0 = (unsigned)y0 < 64u, vy1 = (unsigned)y1 < 64u;
    bool vx0 = (unsigned)x0i < 64u, vx1 = (unsigned)x1 < 64u;

    float w00 = (vy0 && vx0) ? wy0 * wx0 * mask : 0.f;
    float w01 = (vy0 && vx1) ? wy0 * wx1 * mask : 0.f;
    float w10 = (vy1 && vx0) ? wy1 * wx0 * mask : 0.f;
    float w11 = (vy1 && vx1) ? wy1 * wx1 * mask : 0.f;

    int yc0 = min(max(y0, 0), 63), yc1 = min(max(y1, 0), 63);
    int xc0 = min(max(x0i, 0), 63), xc1 = min(max(x1, 0), 63);
    int i00 = yc0 * 64 + xc0, i01 = yc0 * 64 + xc1;
    int i10 = yc1 * 64 + xc0, i11 = yc1 * 64 + xc1;

    const float* xb = x + ((size_t)b * CC + g * 8) * HW;
    float* out = g_smp + ((((size_t)b * CC + g * 8) * K2) + k) * HW + p;
#pragma unroll
    for (int c = 0; c < 8; ++c) {
        const float* xc = xb + (size_t)c * HW;
        float v = w00 * xc[i00] + w01 * xc[i01] + w10 * xc[i10] + w11 * xc[i11];
        out[(size_t)c * K2 * HW] = v;
    }
}

// ---------------------------------------------------------------------------
// Kernel 3: out[b,o,p] = bias[o] + sum_ck smp[b,ck,p] * W[o,ck]
// Block: 256 threads -> 112 O x 128 px. Thread tile: 7 oc x 8 px. K-chunk 16.
// ---------------------------------------------------------------------------
__global__ __launch_bounds__(256) void k3_gemm(const float* __restrict__ w2,
                                               const float* __restrict__ bias,
                                               float* __restrict__ out)
{
    const int pt = blockIdx.x;       // 0..31
    const int b  = blockIdx.y;       // 0..7
    const int t  = threadIdx.x;
    const int pxg = t & 15;          // 16 groups * 8 px
    const int ocg = t >> 4;          // 16 groups * 7 oc
    const int p0  = pt * 128;
    const int px0 = pxg * 8;

    __shared__ __align__(16) float ss[16 * 128];   // [ckl][px]
    __shared__ float ws2[16 * 113];                // [ckl][o] pad

    float acc[7][8];
#pragma unroll
    for (int j = 0; j < 7; ++j)
#pragma unroll
        for (int i = 0; i < 8; ++i) acc[j][i] = 0.f;

    const float* sb = g_smp + (size_t)b * CK * HW + p0;

    for (int ck0 = 0; ck0 < CK; ck0 += 16) {
        __syncthreads();
        // sampled tile: 16 ck x 128 px (2048 = 8*256), coalesced
        {
            int idx = t;
#pragma unroll
            for (int i = 0; i < 8; ++i, idx += 256) {
                int pxl = idx & 127;
                int ckl = idx >> 7;
                ss[ckl * 128 + pxl] = sb[(size_t)(ck0 + ckl) * HW + pxl];
            }
        }
        // weight tile: 16 ck x 112 o (1792 = 7*256)
        {
            int idx = t;
#pragma unroll
            for (int i = 0; i < 7; ++i, idx += 256) {
                int ckl = idx & 15;
                int o   = idx >> 4;
                ws2[ckl * 113 + o] = w2[(size_t)o * CK + ck0 + ckl];
            }
        }
        __syncthreads();

#pragma unroll
        for (int ckl = 0; ckl < 16; ++ckl) {
            float4 sa = *(const float4*)(&ss[ckl * 128 + px0]);
            float4 sc = *(const float4*)(&ss[ckl * 128 + px0 + 4]);
            const float* wr = &ws2[ckl * 113 + ocg * 7];
#pragma unroll
            for (int j = 0; j < 7; ++j) {
                float wv = wr[j];
                acc[j][0] = fmaf(wv, sa.x, acc[j][0]);
                acc[j][1] = fmaf(wv, sa.y, acc[j][1]);
                acc[j][2] = fmaf(wv, sa.z, acc[j][2]);
                acc[j][3] = fmaf(wv, sa.w, acc[j][3]);
                acc[j][4] = fmaf(wv, sc.x, acc[j][4]);
                acc[j][5] = fmaf(wv, sc.y, acc[j][5]);
                acc[j][6] = fmaf(wv, sc.z, acc[j][6]);
                acc[j][7] = fmaf(wv, sc.w, acc[j][7]);
            }
        }
    }

#pragma unroll
    for (int j = 0; j < 7; ++j) {
        int o = ocg * 7 + j;
        float bv = bias[o];
        float* dst = &out[(((size_t)b * OO + o) * HW) + p0 + px0];
        float4 v0 = make_float4(acc[j][0] + bv, acc[j][1] + bv,
                                acc[j][2] + bv, acc[j][3] + bv);
        float4 v1 = make_float4(acc[j][4] + bv, acc[j][5] + bv,
                                acc[j][6] + bv, acc[j][7] + bv);
        *(float4*)(dst)     = v0;
        *(float4*)(dst + 4) = v1;
    }
}

// ---------------------------------------------------------------------------
extern "C" void kernel_launch(void* const* d_in, const int* in_sizes, int n_in,
                              void* d_out, int out_size)
{
    const float* x  = (const float*)d_in[0];   // (8,112,64,64)
    const float* pw = (const float*)d_in[1];   // (378,112,3,3)
    const float* pb = (const float*)d_in[2];   // (378,)
    const float* w  = (const float*)d_in[3];   // (112,112,3,3)
    const float* bs = (const float*)d_in[4];   // (112,)
    float* out = (float*)d_out;                // (8,112,64,64)

    dim3 g1(6, 32, 8);
    k1_pgconv<<<g1, 256>>>(x, pw, pb);

    const int tot2 = BB * GG * K2 * HW;
    k2_sample<<<(tot2 + 255) / 256, 256>>>(x);

    dim3 g3(32, 8);
    k3_gemm<<<g3, 256>>>(w, bs, out);
}

// round 4
// speedup vs baseline: 1.2357x; 1.0176x over previous
#include <cuda_runtime.h>
#include <math.h>

// ---------------------------------------------------------------------------
// DeformableConv2d: B=8, C=112, H=W=64, O=112, K=3, G=14, stride=1, pad=1
// pg channels: 378 = 252 offsets (interleaved dy/dx per (g,k)) + 126 mask
// ---------------------------------------------------------------------------

#define BB 8
#define CC 112
#define HH 64
#define WW 64
#define OO 112
#define GG 14
#define K2 9
#define PGC 378            // 3*G*K2
#define HW 4096            // 64*64
#define CK 1008            // C*K2

// scratch (allocation-free rule: static __device__ arrays)
__device__ float g_pg[BB * PGC * HW];          // 47.25 MiB
__device__ float g_smp[BB * CC * K2 * HW];     // 126 MiB

// ---------------------------------------------------------------------------
// Kernel 1: pg = conv3x3(x, pg_weight, pad=1) + pg_bias
// Block: 256 threads -> 64 oc x 128 px (2 output rows). c-chunks of 8.
// Thread tile: 4 oc x 8 contiguous px. All fill indexing is shift/and only.
// x-values read via LDS.128/LDS.64 (bank-conflict-free, 16B-aligned rows).
// ---------------------------------------------------------------------------
__global__ __launch_bounds__(256) void k1_pgconv(const float* __restrict__ x,
                                                 const float* __restrict__ pw,
                                                 const float* __restrict__ pb)
{
    const int ocTile = blockIdx.x;     // 0..5  (6*64 = 384 >= 378)
    const int rp     = blockIdx.y;     // 0..31 row pair
    const int b      = blockIdx.z;     // 0..7
    const int t      = threadIdx.x;
    const int oh0    = rp * 2;

    const int pg   = t & 15;           // 16 pixel groups
    const int og   = t >> 4;           // 16 oc groups
    const int r    = pg >> 3;          // 0/1 : which output row
    const int col0 = (pg & 7) * 8;     // 8 contiguous columns
    const int ocl0 = og * 4;
    const int oc0  = ocTile * 64;

    // xs rows: input rows oh0-1 .. oh0+2 ; row stride 68 floats = 272B (16B mult)
    __shared__ __align__(16) float xs[4][8][68];
    __shared__ __align__(16) float ws[72 * 68];

    // halo columns (iw=-1 at [0], iw=64 at [65]) are always OOB -> zero once
    if (t < 64) {
        int rr = t >> 4, cl = (t >> 1) & 7, side = t & 1;
        xs[rr][cl][side * 65] = 0.f;
    }

    float acc[4][8];
#pragma unroll
    for (int j = 0; j < 4; ++j)
#pragma unroll
        for (int i = 0; i < 8; ++i) acc[j][i] = 0.f;

    for (int c0 = 0; c0 < CC; c0 += 8) {
        __syncthreads();
        // ---- input tile: 4 rows x 8 ch x 64 inner cols (2048 = 8*256)
        {
            int idx = t;
#pragma unroll
            for (int i = 0; i < 8; ++i, idx += 256) {
                int col = idx & 63;
                int cl  = (idx >> 6) & 7;
                int rr  = idx >> 9;
                int ih  = oh0 - 1 + rr;
                float v = 0.f;
                if ((unsigned)ih < 64u)
                    v = x[(((size_t)b * CC + c0 + cl) * HH + ih) * WW + col];
                xs[rr][cl][col + 1] = v;
            }
        }
        // ---- weight tile: 72 ck x 64 oc (4608 = 18*256), [ck][oc] pad 68
        {
            int idx = t;
#pragma unroll
            for (int i = 0; i < 18; ++i, idx += 256) {
                int ocl = idx & 63;
                int ck  = idx >> 6;
                int oc  = oc0 + ocl;
                float v = (oc < PGC) ? pw[(size_t)oc * CK + c0 * 9 + ck] : 0.f;
                ws[ck * 68 + ocl] = v;
            }
        }
        __syncthreads();

#pragma unroll
        for (int cl = 0; cl < 8; ++cl) {
#pragma unroll
            for (int ky = 0; ky < 3; ++ky) {
                // 10 consecutive floats: 2x LDS.128 + 1x LDS.64 (all aligned:
                // col0 multiple of 8 floats = 32B; row stride 272B)
                const float* xrow = &xs[r + ky][cl][col0];
                const float4 xa = *(const float4*)(xrow);
                const float4 xb = *(const float4*)(xrow + 4);
                const float2 xc = *(const float2*)(xrow + 8);
                const float xv[10] = { xa.x, xa.y, xa.z, xa.w,
                                       xb.x, xb.y, xb.z, xb.w,
                                       xc.x, xc.y };
#pragma unroll
                for (int kx = 0; kx < 3; ++kx) {
                    const float4 wv =
                        *(const float4*)(&ws[(cl * 9 + ky * 3 + kx) * 68 + ocl0]);
#pragma unroll
                    for (int i = 0; i < 8; ++i) {
                        acc[0][i] = fmaf(wv.x, xv[i + kx], acc[0][i]);
                        acc[1][i] = fmaf(wv.y, xv[i + kx], acc[1][i]);
                        acc[2][i] = fmaf(wv.z, xv[i + kx], acc[2][i]);
                        acc[3][i] = fmaf(wv.w, xv[i + kx], acc[3][i]);
                    }
                }
            }
        }
    }

#pragma unroll
    for (int j = 0; j < 4; ++j) {
        int oc = oc0 + ocl0 + j;
        if (oc < PGC) {
            float bv = pb[oc];
            float* dst = &g_pg[(((size_t)b * PGC + oc) * HH + oh0 + r) * WW + col0];
            float4 v0 = make_float4(acc[j][0] + bv, acc[j][1] + bv,
                                    acc[j][2] + bv, acc[j][3] + bv);
            float4 v1 = make_float4(acc[j][4] + bv, acc[j][5] + bv,
                                    acc[j][6] + bv, acc[j][7] + bv);
            *(float4*)(dst)     = v0;
            *(float4*)(dst + 4) = v1;
        }
    }
}

// ---------------------------------------------------------------------------
// Kernel 2: bilinear sampling * sigmoid(mask)
// One thread per (b, g, k, pixel). dy = pg[g*18+2k], dx = pg[g*18+2k+1]
// (interleaved!), mask = sigmoid(pg[252 + g*9 + k]).
// Output layout: g_smp[b][c][k][p]
// ---------------------------------------------------------------------------
__global__ __launch_bounds__(256) void k2_sample(const float* __restrict__ x)
{
    int gid = blockIdx.x * 256 + threadIdx.x;
    const int TOT = BB * GG * K2 * HW;   // 4,128,768
    if (gid >= TOT) return;

    int p    = gid & (HW - 1);
    int rest = gid >> 12;
    int gk   = rest % (GG * K2);
    int b    = rest / (GG * K2);
    int g    = gk / 9;
    int k    = gk - g * 9;
    int oh   = p >> 6, ow = p & 63;

    const float* pgb = g_pg + (size_t)b * PGC * HW;
    float dy = pgb[(g * 18 + 2 * k) * HW + p];
    float dx = pgb[(g * 18 + 2 * k + 1) * HW + p];
    float m  = pgb[(252 + gk) * HW + p];
    float mask = 1.f / (1.f + expf(-m));

    float yy = (float)(oh - 1 + k / 3) + dy;
    float xx = (float)(ow - 1 + k % 3) + dx;
    float y0f = floorf(yy), x0f = floorf(xx);
    float wy1 = yy - y0f, wx1 = xx - x0f;
    float wy0 = 1.f - wy1, wx0 = 1.f - wx1;
    int y0 = (int)y0f, x0i = (int)x0f;
    int y1 = y0 + 1, x1 = x0i + 1;
    bool vy0 = (unsigned)y0 < 64u, vy1 = (unsigned)y1 < 64u;
    bool vx0 = (unsigned)x0i < 64u, vx1 = (unsigned)x1 < 64u;

    float w00 = (vy0 && vx0) ? wy0 * wx0 * mask : 0.f;
    float w01 = (vy0 && vx1) ? wy0 * wx1 * mask : 0.f;
    float w10 = (vy1 && vx0) ? wy1 * wx0 * mask : 0.f;
    float w11 = (vy1 && vx1) ? wy1 * wx1 * mask : 0.f;

    int yc0 = min(max(y0, 0), 63), yc1 = min(max(y1, 0), 63);
    int xc0 = min(max(x0i, 0), 63), xc1 = min(max(x1, 0), 63);
    int i00 = yc0 * 64 + xc0, i01 = yc0 * 64 + xc1;
    int i10 = yc1 * 64 + xc0, i11 = yc1 * 64 + xc1;

    const float* xb = x + ((size_t)b * CC + g * 8) * HW;
    float* out = g_smp + ((((size_t)b * CC + g * 8) * K2) + k) * HW + p;
#pragma unroll
    for (int c = 0; c < 8; ++c) {
        const float* xc = xb + (size_t)c * HW;
        float v = w00 * xc[i00] + w01 * xc[i01] + w10 * xc[i10] + w11 * xc[i11];
        out[(size_t)c * K2 * HW] = v;
    }
}

// ---------------------------------------------------------------------------
// Kernel 3: out[b,o,p] = bias[o] + sum_ck smp[b,ck,p] * W[o,ck]
// Block: 256 threads -> 112 O x 128 px. Thread tile: 7 oc x 8 px. K-chunk 16.
// ---------------------------------------------------------------------------
__global__ __launch_bounds__(256) void k3_gemm(const float* __restrict__ w2,
                                               const float* __restrict__ bias,
                                               float* __restrict__ out)
{
    const int pt = blockIdx.x;       // 0..31
    const int b  = blockIdx.y;       // 0..7
    const int t  = threadIdx.x;
    const int pxg = t & 15;          // 16 groups * 8 px
    const int ocg = t >> 4;          // 16 groups * 7 oc
    const int p0  = pt * 128;
    const int px0 = pxg * 8;

    __shared__ __align__(16) float ss[16 * 128];   // [ckl][px]
    __shared__ float ws2[16 * 113];                // [ckl][o] pad

    float acc[7][8];
#pragma unroll
    for (int j = 0; j < 7; ++j)
#pragma unroll
        for (int i = 0; i < 8; ++i) acc[j][i] = 0.f;

    const float* sb = g_smp + (size_t)b * CK * HW + p0;

    for (int ck0 = 0; ck0 < CK; ck0 += 16) {
        __syncthreads();
        // sampled tile: 16 ck x 128 px (2048 = 8*256), coalesced
        {
            int idx = t;
#pragma unroll
            for (int i = 0; i < 8; ++i, idx += 256) {
                int pxl = idx & 127;
                int ckl = idx >> 7;
                ss[ckl * 128 + pxl] = sb[(size_t)(ck0 + ckl) * HW + pxl];
            }
        }
        // weight tile: 16 ck x 112 o (1792 = 7*256)
        {
            int idx = t;
#pragma unroll
            for (int i = 0; i < 7; ++i, idx += 256) {
                int ckl = idx & 15;
                int o   = idx >> 4;
                ws2[ckl * 113 + o] = w2[(size_t)o * CK + ck0 + ckl];
            }
        }
        __syncthreads();

#pragma unroll
        for (int ckl = 0; ckl < 16; ++ckl) {
            float4 sa = *(const float4*)(&ss[ckl * 128 + px0]);
            float4 sc = *(const float4*)(&ss[ckl * 128 + px0 + 4]);
            const float* wr = &ws2[ckl * 113 + ocg * 7];
#pragma unroll
            for (int j = 0; j < 7; ++j) {
                float wv = wr[j];
                acc[j][0] = fmaf(wv, sa.x, acc[j][0]);
                acc[j][1] = fmaf(wv, sa.y, acc[j][1]);
                acc[j][2] = fmaf(wv, sa.z, acc[j][2]);
                acc[j][3] = fmaf(wv, sa.w, acc[j][3]);
                acc[j][4] = fmaf(wv, sc.x, acc[j][4]);
                acc[j][5] = fmaf(wv, sc.y, acc[j][5]);
                acc[j][6] = fmaf(wv, sc.z, acc[j][6]);
                acc[j][7] = fmaf(wv, sc.w, acc[j][7]);
            }
        }
    }

#pragma unroll
    for (int j = 0; j < 7; ++j) {
        int o = ocg * 7 + j;
        float bv = bias[o];
        float* dst = &out[(((size_t)b * OO + o) * HW) + p0 + px0];
        float4 v0 = make_float4(acc[j][0] + bv, acc[j][1] + bv,
                                acc[j][2] + bv, acc[j][3] + bv);
        float4 v1 = make_float4(acc[j][4] + bv, acc[j][5] + bv,
                                acc[j][6] + bv, acc[j][7] + bv);
        *(float4*)(dst)     = v0;
        *(float4*)(dst + 4) = v1;
    }
}

// ---------------------------------------------------------------------------
extern "C" void kernel_launch(void* const* d_in, const int* in_sizes, int n_in,
                              void* d_out, int out_size)
{
    const float* x  = (const float*)d_in[0];   // (8,112,64,64)
    const float* pw = (const float*)d_in[1];   // (378,112,3,3)
    const float* pb = (const float*)d_in[2];   // (378,)
    const float* w  = (const float*)d_in[3];   // (112,112,3,3)
    const float* bs = (const float*)d_in[4];   // (112,)
    float* out = (float*)d_out;                // (8,112,64,64)

    dim3 g1(6, 32, 8);
    k1_pgconv<<<g1, 256>>>(x, pw, pb);

    const int tot2 = BB * GG * K2 * HW;
    k2_sample<<<(tot2 + 255) / 256, 256>>>(x);

    dim3 g3(32, 8);
    k3_gemm<<<g3, 256>>>(w, bs, out);
}

// round 9
// speedup vs baseline: 1.3335x; 1.0792x over previous
#include <cuda_runtime.h>
#include <cstdint>
#include <math.h>

// ---------------------------------------------------------------------------
// DeformableConv2d: B=8, C=112, H=W=64, O=112, K=3, G=14, stride=1, pad=1
// pg channels: 378 = 252 offsets (interleaved dy/dx per (g,k)) + 126 mask
// ---------------------------------------------------------------------------

#define BB 8
#define CC 112
#define HH 64
#define WW 64
#define OO 112
#define GG 14
#define K2 9
#define PGC 378            // 3*G*K2
#define HW 4096            // 64*64
#define CK 1008            // C*K2

// scratch (allocation-free rule: static __device__ arrays)
__device__ float g_pg[BB * PGC * HW];          // 47.25 MiB
__device__ float g_smp[BB * CC * K2 * HW];     // 126 MiB

// ---------------------------------------------------------------------------
// Kernel 1: pg = conv3x3(x, pg_weight, pad=1) + pg_bias
// Block: 256 threads -> 64 oc x 128 px (2 output rows). c-chunks of 8.
// Thread map (SWAPPED vs R2/R4): og = t&15, pg = t>>4.
//  -> per 8-lane LDS subphase: x reads are single-address broadcast,
//     w reads are 8 consecutive float4s spanning 128B (conflict-free).
// Thread tile: 4 oc x 8 px.
// ---------------------------------------------------------------------------
__global__ __launch_bounds__(256) void k1_pgconv(const float* __restrict__ x,
                                                 const float* __restrict__ pw,
                                                 const float* __restrict__ pb)
{
    const int ocTile = blockIdx.x;     // 0..5  (6*64 = 384 >= 378)
    const int rp     = blockIdx.y;     // 0..31 row pair
    const int b      = blockIdx.z;     // 0..7
    const int t      = threadIdx.x;
    const int oh0    = rp * 2;

    const int og   = t & 15;           // 16 oc groups * 4 oc
    const int pg   = t >> 4;           // 16 pixel groups
    const int r    = pg >> 3;          // 0/1 : which output row
    const int col0 = (pg & 7) * 8;     // 8 contiguous columns
    const int ocl0 = og * 4;
    const int oc0  = ocTile * 64;

    // xs rows: input rows oh0-1 .. oh0+2 ; row stride 68 floats = 272B (16B mult)
    __shared__ __align__(16) float xs[4][8][68];
    __shared__ __align__(16) float ws[72 * 64];   // [ck][oc], 64 = no pad needed

    // halo columns (iw=-1 at [0], iw=64 at [65]) always OOB -> zero once
    if (t < 64) {
        int rr = t >> 4, cl = (t >> 1) & 7, side = t & 1;
        xs[rr][cl][side * 65] = 0.f;
    }

    float acc[4][8];
#pragma unroll
    for (int j = 0; j < 4; ++j)
#pragma unroll
        for (int i = 0; i < 8; ++i) acc[j][i] = 0.f;

    for (int c0 = 0; c0 < CC; c0 += 8) {
        __syncthreads();
        // ---- input tile: 4 rows x 8 ch x 64 inner cols (2048 = 8*256)
        {
            int idx = t;
#pragma unroll
            for (int i = 0; i < 8; ++i, idx += 256) {
                int col = idx & 63;
                int cl  = (idx >> 6) & 7;
                int rr  = idx >> 9;
                int ih  = oh0 - 1 + rr;
                float v = 0.f;
                if ((unsigned)ih < 64u)
                    v = x[(((size_t)b * CC + c0 + cl) * HH + ih) * WW + col];
                xs[rr][cl][col + 1] = v;
            }
        }
        // ---- weight tile: 72 ck x 64 oc (4608 = 18*256), [ck][oc]
        {
            int idx = t;
#pragma unroll
            for (int i = 0; i < 18; ++i, idx += 256) {
                int ocl = idx & 63;
                int ck  = idx >> 6;
                int oc  = oc0 + ocl;
                float v = (oc < PGC) ? pw[(size_t)oc * CK + c0 * 9 + ck] : 0.f;
                ws[ck * 64 + ocl] = v;
            }
        }
        __syncthreads();

#pragma unroll
        for (int cl = 0; cl < 8; ++cl) {
#pragma unroll
            for (int ky = 0; ky < 3; ++ky) {
                // 10 consecutive floats: 2x LDS.128 + 1x LDS.64 — all lanes of a
                // subphase share pg -> broadcast (single address per subphase)
                const float* xrow = &xs[r + ky][cl][col0];
                const float4 xa = *(const float4*)(xrow);
                const float4 xb = *(const float4*)(xrow + 4);
                const float2 xc = *(const float2*)(xrow + 8);
                const float xv[10] = { xa.x, xa.y, xa.z, xa.w,
                                       xb.x, xb.y, xb.z, xb.w,
                                       xc.x, xc.y };
#pragma unroll
                for (int kx = 0; kx < 3; ++kx) {
                    // subphase lanes og=0..7 read float4s at ocl0=0,4,..,28
                    // -> bytes 0..127 of a 256B-aligned row: conflict-free
                    const float4 wv =
                        *(const float4*)(&ws[(cl * 9 + ky * 3 + kx) * 64 + ocl0]);
#pragma unroll
                    for (int i = 0; i < 8; ++i) {
                        acc[0][i] = fmaf(wv.x, xv[i + kx], acc[0][i]);
                        acc[1][i] = fmaf(wv.y, xv[i + kx], acc[1][i]);
                        acc[2][i] = fmaf(wv.z, xv[i + kx], acc[2][i]);
                        acc[3][i] = fmaf(wv.w, xv[i + kx], acc[3][i]);
                    }
                }
            }
        }
    }

#pragma unroll
    for (int j = 0; j < 4; ++j) {
        int oc = oc0 + ocl0 + j;
        if (oc < PGC) {
            float bv = pb[oc];
            float* dst = &g_pg[(((size_t)b * PGC + oc) * HH + oh0 + r) * WW + col0];
            float4 v0 = make_float4(acc[j][0] + bv, acc[j][1] + bv,
                                    acc[j][2] + bv, acc[j][3] + bv);
            float4 v1 = make_float4(acc[j][4] + bv, acc[j][5] + bv,
                                    acc[j][6] + bv, acc[j][7] + bv);
            *(float4*)(dst)     = v0;
            *(float4*)(dst + 4) = v1;
        }
    }
}

// ---------------------------------------------------------------------------
// Kernel 2: bilinear sampling * sigmoid(mask)
// One thread per (b, g, k, pixel). dy = pg[g*18+2k], dx = pg[g*18+2k+1]
// (interleaved!), mask = sigmoid(pg[252 + g*9 + k]).
// Output layout: g_smp[b][c][k][p]
// ---------------------------------------------------------------------------
__global__ __launch_bounds__(256) void k2_sample(const float* __restrict__ x)
{
    int gid = blockIdx.x * 256 + threadIdx.x;
    const int TOT = BB * GG * K2 * HW;   // 4,128,768
    if (gid >= TOT) return;

    int p    = gid & (HW - 1);
    int rest = gid >> 12;
    int gk   = rest % (GG * K2);
    int b    = rest / (GG * K2);
    int g    = gk / 9;
    int k    = gk - g * 9;
    int oh   = p >> 6, ow = p & 63;

    const float* pgb = g_pg + (size_t)b * PGC * HW;
    float dy = pgb[(g * 18 + 2 * k) * HW + p];
    float dx = pgb[(g * 18 + 2 * k + 1) * HW + p];
    float m  = pgb[(252 + gk) * HW + p];
    float mask = 1.f / (1.f + expf(-m));

    float yy = (float)(oh - 1 + k / 3) + dy;
    float xx = (float)(ow - 1 + k % 3) + dx;
    float y0f = floorf(yy), x0f = floorf(xx);
    float wy1 = yy - y0f, wx1 = xx - x0f;
    float wy0 = 1.f - wy1, wx0 = 1.f - wx1;
    int y0 = (int)y0f, x0i = (int)x0f;
    int y1 = y0 + 1, x1 = x0i + 1;
    bool vy0 = (unsigned)y0 < 64u, vy1 = (unsigned)y1 < 64u;
    bool vx0 = (unsigned)x0i < 64u, vx1 = (unsigned)x1 < 64u;

    float w00 = (vy0 && vx0) ? wy0 * wx0 * mask : 0.f;
    float w01 = (vy0 && vx1) ? wy0 * wx1 * mask : 0.f;
    float w10 = (vy1 && vx0) ? wy1 * wx0 * mask : 0.f;
    float w11 = (vy1 && vx1) ? wy1 * wx1 * mask : 0.f;

    int yc0 = min(max(y0, 0), 63), yc1 = min(max(y1, 0), 63);
    int xc0 = min(max(x0i, 0), 63), xc1 = min(max(x1, 0), 63);
    int i00 = yc0 * 64 + xc0, i01 = yc0 * 64 + xc1;
    int i10 = yc1 * 64 + xc0, i11 = yc1 * 64 + xc1;

    const float* xb = x + ((size_t)b * CC + g * 8) * HW;
    float* out = g_smp + ((((size_t)b * CC + g * 8) * K2) + k) * HW + p;
#pragma unroll
    for (int c = 0; c < 8; ++c) {
        const float* xc = xb + (size_t)c * HW;
        float v = w00 * xc[i00] + w01 * xc[i01] + w10 * xc[i10] + w11 * xc[i11];
        out[(size_t)c * K2 * HW] = v;
    }
}

// ---------------------------------------------------------------------------
// Kernel 3: out[b,o,p] = bias[o] + sum_ck smp[b,ck,p] * W[o,ck]
// Block: 256 threads -> 112 O x 128 px. Thread tile: 7 oc x 8 px. K-chunk 16.
// ---------------------------------------------------------------------------
__global__ __launch_bounds__(256) void k3_gemm(const float* __restrict__ w2,
                                               const float* __restrict__ bias,
                                               float* __restrict__ out)
{
    const int pt = blockIdx.x;       // 0..31
    const int b  = blockIdx.y;       // 0..7
    const int t  = threadIdx.x;
    const int pxg = t & 15;          // 16 groups * 8 px
    const int ocg = t >> 4;          // 16 groups * 7 oc
    const int p0  = pt * 128;
    const int px0 = pxg * 8;

    __shared__ __align__(16) float ss[16 * 128];   // [ckl][px]
    __shared__ float ws2[16 * 113];                // [ckl][o] pad

    float acc[7][8];
#pragma unroll
    for (int j = 0; j < 7; ++j)
#pragma unroll
        for (int i = 0; i < 8; ++i) acc[j][i] = 0.f;

    const float* sb = g_smp + (size_t)b * CK * HW + p0;

    for (int ck0 = 0; ck0 < CK; ck0 += 16) {
        __syncthreads();
        {
            int idx = t;
#pragma unroll
            for (int i = 0; i < 8; ++i, idx += 256) {
                int pxl = idx & 127;
                int ckl = idx >> 7;
                ss[ckl * 128 + pxl] = sb[(size_t)(ck0 + ckl) * HW + pxl];
            }
        }
        {
            int idx = t;
#pragma unroll
            for (int i = 0; i < 7; ++i, idx += 256) {
                int ckl = idx & 15;
                int o   = idx >> 4;
                ws2[ckl * 113 + o] = w2[(size_t)o * CK + ck0 + ckl];
            }
        }
        __syncthreads();

#pragma unroll
        for (int ckl = 0; ckl < 16; ++ckl) {
            float4 sa = *(const float4*)(&ss[ckl * 128 + px0]);
            float4 sc = *(const float4*)(&ss[ckl * 128 + px0 + 4]);
            const float* wr = &ws2[ckl * 113 + ocg * 7];
#pragma unroll
            for (int j = 0; j < 7; ++j) {
                float wv = wr[j];
                acc[j][0] = fmaf(wv, sa.x, acc[j][0]);
                acc[j][1] = fmaf(wv, sa.y, acc[j][1]);
                acc[j][2] = fmaf(wv, sa.z, acc[j][2]);
                acc[j][3] = fmaf(wv, sa.w, acc[j][3]);
                acc[j][4] = fmaf(wv, sc.x, acc[j][4]);
                acc[j][5] = fmaf(wv, sc.y, acc[j][5]);
                acc[j][6] = fmaf(wv, sc.z, acc[j][6]);
                acc[j][7] = fmaf(wv, sc.w, acc[j][7]);
            }
        }
    }

#pragma unroll
    for (int j = 0; j < 7; ++j) {
        int o = ocg * 7 + j;
        float bv = bias[o];
        float* dst = &out[(((size_t)b * OO + o) * HW) + p0 + px0];
        float4 v0 = make_float4(acc[j][0] + bv, acc[j][1] + bv,
                                acc[j][2] + bv, acc[j][3] + bv);
        float4 v1 = make_float4(acc[j][4] + bv, acc[j][5] + bv,
                                acc[j][6] + bv, acc[j][7] + bv);
        *(float4*)(dst)     = v0;
        *(float4*)(dst + 4) = v1;
    }
}

// ---------------------------------------------------------------------------
extern "C" void kernel_launch(void* const* d_in, const int* in_sizes, int n_in,
                              void* d_out, int out_size)
{
    const float* x  = (const float*)d_in[0];   // (8,112,64,64)
    const float* pw = (const float*)d_in[1];   // (378,112,3,3)
    const float* pb = (const float*)d_in[2];   // (378,)
    const float* w  = (const float*)d_in[3];   // (112,112,3,3)
    const float* bs = (const float*)d_in[4];   // (112,)
    float* out = (float*)d_out;                // (8,112,64,64)

    dim3 g1(6, 32, 8);
    k1_pgconv<<<g1, 256>>>(x, pw, pb);

    const int tot2 = BB * GG * K2 * HW;
    k2_sample<<<(tot2 + 255) / 256, 256>>>(x);

    dim3 g3(32, 8);
    k3_gemm<<<g3, 256>>>(w, bs, out);
}